// round 1
// baseline (speedup 1.0000x reference)
#include <cuda_runtime.h>
#include <cuda_bf16.h>

// Problem constants (fixed for this problem instance)
#define T_  1024
#define H_  2048
#define I_  768
#define E_  32
#define K_  4
#define NA  (T_*K_)   // 4096 assignment rows

// Tiling
#define TM  64
#define TN  64
#define TKD 16

// ---- device scratch (static; allocation-free per harness rules) ----
__device__ int   g_counts[E_];
__device__ int   g_offsets[E_];
__device__ int   g_cursor[E_];
__device__ int   g_perm[NA];                       // sorted-by-expert assignment ids (t*K+k)
__device__ float g_h[(size_t)NA * I_];             // intermediate silu(gate)*up, 12.6 MB
__device__ float g_yp[(size_t)NA * H_];            // per-slot down-proj output, 33.5 MB

// ---------------- routing ----------------
__global__ void k_zero() {
    int i = threadIdx.x;
    if (i < E_) { g_counts[i] = 0; g_cursor[i] = 0; }
}

__global__ void k_count(const int* __restrict__ ids) {
    int i = blockIdx.x * blockDim.x + threadIdx.x;
    if (i < NA) atomicAdd(&g_counts[ids[i]], 1);
}

__global__ void k_scan() {
    if (threadIdx.x == 0) {
        int acc = 0;
        for (int e = 0; e < E_; e++) { g_offsets[e] = acc; acc += g_counts[e]; }
    }
}

__global__ void k_scatter(const int* __restrict__ ids) {
    int i = blockIdx.x * blockDim.x + threadIdx.x;
    if (i < NA) {
        int e = ids[i];
        int p = atomicAdd(&g_cursor[e], 1);
        g_perm[g_offsets[e] + p] = i;   // i = t*K + k
    }
}

// ---------------- gate+up fused GEMM ----------------
// For each expert e, rows = gathered x-rows; computes
//   h = silu(x @ Wg_e^T) * (x @ Wu_e^T)   -> g_h[sorted_row, I]
__global__ __launch_bounds__(256) void k_gateup(
    const float* __restrict__ x,
    const float* __restrict__ Wg,
    const float* __restrict__ Wu)
{
    int e    = blockIdx.z;
    int cnt  = g_counts[e];
    int row0 = blockIdx.y * TM;
    if (row0 >= cnt) return;
    int off  = g_offsets[e];
    int col0 = blockIdx.x * TN;

    __shared__ float As[TKD][TM + 4];
    __shared__ float Bg[TKD][TN + 4];
    __shared__ float Bu[TKD][TN + 4];
    __shared__ int   toks[TM];

    int tid = threadIdx.x;
    int tx  = tid & 15;
    int ty  = tid >> 4;

    if (tid < TM) {
        int r  = row0 + tid;
        int pv = (r < cnt) ? g_perm[off + r] : 0;
        toks[tid] = pv >> 2;   // token id (K_=4)
    }
    __syncthreads();

    const float* wg = Wg + (size_t)e * I_ * H_;
    const float* wu = Wu + (size_t)e * I_ * H_;

    float ag[4][4], au[4][4];
#pragma unroll
    for (int i = 0; i < 4; i++)
#pragma unroll
        for (int j = 0; j < 4; j++) { ag[i][j] = 0.f; au[i][j] = 0.f; }

    int lr = tid >> 2;         // 0..63 (row within tile)
    int lc = (tid & 3) * 4;    // 0,4,8,12 (k within k-tile)

    for (int k0 = 0; k0 < H_; k0 += TKD) {
        int t = toks[lr];
        float4 av = *reinterpret_cast<const float4*>(&x[(size_t)t * H_ + k0 + lc]);
        As[lc+0][lr] = av.x; As[lc+1][lr] = av.y; As[lc+2][lr] = av.z; As[lc+3][lr] = av.w;

        float4 gv = *reinterpret_cast<const float4*>(&wg[(size_t)(col0 + lr) * H_ + k0 + lc]);
        Bg[lc+0][lr] = gv.x; Bg[lc+1][lr] = gv.y; Bg[lc+2][lr] = gv.z; Bg[lc+3][lr] = gv.w;

        float4 uv = *reinterpret_cast<const float4*>(&wu[(size_t)(col0 + lr) * H_ + k0 + lc]);
        Bu[lc+0][lr] = uv.x; Bu[lc+1][lr] = uv.y; Bu[lc+2][lr] = uv.z; Bu[lc+3][lr] = uv.w;
        __syncthreads();

#pragma unroll
        for (int kk = 0; kk < TKD; kk++) {
            float a[4], bg[4], bu[4];
#pragma unroll
            for (int i = 0; i < 4; i++) a[i] = As[kk][ty * 4 + i];
#pragma unroll
            for (int j = 0; j < 4; j++) { bg[j] = Bg[kk][tx * 4 + j]; bu[j] = Bu[kk][tx * 4 + j]; }
#pragma unroll
            for (int i = 0; i < 4; i++)
#pragma unroll
                for (int j = 0; j < 4; j++) {
                    ag[i][j] += a[i] * bg[j];
                    au[i][j] += a[i] * bu[j];
                }
        }
        __syncthreads();
    }

#pragma unroll
    for (int i = 0; i < 4; i++) {
        int r = row0 + ty * 4 + i;
        if (r < cnt) {
            size_t gr = (size_t)(off + r);
#pragma unroll
            for (int j = 0; j < 4; j++) {
                float g = ag[i][j], u = au[i][j];
                float s = g / (1.f + __expf(-g));   // silu
                g_h[gr * I_ + col0 + tx * 4 + j] = s * u;
            }
        }
    }
}

// ---------------- down projection GEMM ----------------
// out[pv, n] = ew[pv] * (h[row] @ Wd_e^T)[n]   -> g_yp[pv, H]
__global__ __launch_bounds__(256) void k_down(
    const float* __restrict__ Wd,
    const float* __restrict__ ew)
{
    int e    = blockIdx.z;
    int cnt  = g_counts[e];
    int row0 = blockIdx.y * TM;
    if (row0 >= cnt) return;
    int off  = g_offsets[e];
    int col0 = blockIdx.x * TN;   // over H_

    __shared__ float As[TKD][TM + 4];
    __shared__ float Bs[TKD][TN + 4];
    __shared__ int   pvS[TM];

    int tid = threadIdx.x;
    int tx  = tid & 15;
    int ty  = tid >> 4;

    if (tid < TM) {
        int r = row0 + tid;
        pvS[tid] = (r < cnt) ? g_perm[off + r] : 0;
    }
    __syncthreads();

    const float* wd = Wd + (size_t)e * H_ * I_;

    float acc[4][4];
#pragma unroll
    for (int i = 0; i < 4; i++)
#pragma unroll
        for (int j = 0; j < 4; j++) acc[i][j] = 0.f;

    int lr = tid >> 2;
    int lc = (tid & 3) * 4;
    int grA = off + row0 + lr;
    if (grA > NA - 1) grA = NA - 1;   // clamp padded rows (values discarded)

    for (int k0 = 0; k0 < I_; k0 += TKD) {
        float4 av = *reinterpret_cast<const float4*>(&g_h[(size_t)grA * I_ + k0 + lc]);
        As[lc+0][lr] = av.x; As[lc+1][lr] = av.y; As[lc+2][lr] = av.z; As[lc+3][lr] = av.w;

        float4 bv = *reinterpret_cast<const float4*>(&wd[(size_t)(col0 + lr) * I_ + k0 + lc]);
        Bs[lc+0][lr] = bv.x; Bs[lc+1][lr] = bv.y; Bs[lc+2][lr] = bv.z; Bs[lc+3][lr] = bv.w;
        __syncthreads();

#pragma unroll
        for (int kk = 0; kk < TKD; kk++) {
            float a[4], b[4];
#pragma unroll
            for (int i = 0; i < 4; i++) a[i] = As[kk][ty * 4 + i];
#pragma unroll
            for (int j = 0; j < 4; j++) b[j] = Bs[kk][tx * 4 + j];
#pragma unroll
            for (int i = 0; i < 4; i++)
#pragma unroll
                for (int j = 0; j < 4; j++) acc[i][j] += a[i] * b[j];
        }
        __syncthreads();
    }

#pragma unroll
    for (int i = 0; i < 4; i++) {
        int r = row0 + ty * 4 + i;
        if (r < cnt) {
            int   pv = pvS[ty * 4 + i];
            float w  = ew[pv];
#pragma unroll
            for (int j = 0; j < 4; j++)
                g_yp[(size_t)pv * H_ + col0 + tx * 4 + j] = w * acc[i][j];
        }
    }
}

// ---------------- combine K slots per token ----------------
__global__ void k_combine(float* __restrict__ y) {
    int i = blockIdx.x * blockDim.x + threadIdx.x;   // over T_*H_
    if (i < T_ * H_) {
        int t = i / H_;
        int h = i - t * H_;
        float s = 0.f;
#pragma unroll
        for (int k = 0; k < K_; k++)
            s += g_yp[(size_t)(t * K_ + k) * H_ + h];
        y[i] = s;
    }
}

// ---------------- launch ----------------
extern "C" void kernel_launch(void* const* d_in, const int* in_sizes, int n_in,
                              void* d_out, int out_size)
{
    const float* x   = (const float*)d_in[0];
    const float* Wg  = (const float*)d_in[1];
    const float* Wu  = (const float*)d_in[2];
    const float* Wd  = (const float*)d_in[3];
    const int*   ids = (const int*)d_in[4];
    const float* ew  = (const float*)d_in[5];
    float*       y   = (float*)d_out;

    k_zero<<<1, 32>>>();
    k_count<<<NA / 256, 256>>>(ids);
    k_scan<<<1, 1>>>();
    k_scatter<<<NA / 256, 256>>>(ids);

    dim3 gA(I_ / TN, NA / TM, E_);   // (12, 64, 32) — most row-tiles early-exit
    k_gateup<<<gA, 256>>>(x, Wg, Wu);

    dim3 gB(H_ / TN, NA / TM, E_);   // (32, 64, 32)
    k_down<<<gB, 256>>>(Wd, ew);

    k_combine<<<(T_ * H_ + 255) / 256, 256>>>(y);
}

// round 3
// speedup vs baseline: 2.1056x; 2.1056x over previous
#include <cuda_runtime.h>
#include <cuda_bf16.h>

// Problem constants
#define T_  1024
#define H_  2048
#define I_  768
#define E_  32
#define K_  4
#define NA  (T_*K_)   // 4096 assignment rows

// GEMM tiling
#define TM  64
#define TN  128
#define KC  32
#define RS  80        // SMEM row stride in bytes (40 bf16) — conflict-free ldmatrix

// ---------------- portable PTX helpers (no sm_103a-only features) ----------------
__device__ __forceinline__ unsigned smem_u32(const void* p) {
    unsigned a;
    asm("{ .reg .u64 t; cvta.to.shared.u64 t, %1; cvt.u32.u64 %0, t; }" : "=r"(a) : "l"(p));
    return a;
}

__device__ __forceinline__ void ldm4(unsigned* d, unsigned a) {
    asm volatile("ldmatrix.sync.aligned.m8n8.x4.shared.b16 {%0,%1,%2,%3}, [%4];"
        : "=r"(d[0]), "=r"(d[1]), "=r"(d[2]), "=r"(d[3]) : "r"(a));
}

__device__ __forceinline__ void mma4(float* c, const unsigned* a, const unsigned* b) {
    asm volatile("mma.sync.aligned.m16n8k16.row.col.f32.bf16.bf16.f32 "
        "{%0,%1,%2,%3},{%4,%5,%6,%7},{%8,%9},{%0,%1,%2,%3};"
        : "+f"(c[0]), "+f"(c[1]), "+f"(c[2]), "+f"(c[3])
        : "r"(a[0]), "r"(a[1]), "r"(a[2]), "r"(a[3]), "r"(b[0]), "r"(b[1]));
}

// split 8 fp32 -> 8 bf16 hi + 8 bf16 lo (packed into uint4 each)
__device__ __forceinline__ void cvt8(float4 a, float4 b, uint4& hi, uint4& lo) {
    float va[8] = {a.x, a.y, a.z, a.w, b.x, b.y, b.z, b.w};
    unsigned hw[4], lw[4];
#pragma unroll
    for (int j = 0; j < 4; j++) {
        float2 f = make_float2(va[2*j], va[2*j+1]);
        __nv_bfloat162 h = __float22bfloat162_rn(f);
        float2 hf = __bfloat1622float2(h);
        __nv_bfloat162 l = __float22bfloat162_rn(make_float2(f.x - hf.x, f.y - hf.y));
        hw[j] = *reinterpret_cast<unsigned*>(&h);
        lw[j] = *reinterpret_cast<unsigned*>(&l);
    }
    hi = make_uint4(hw[0], hw[1], hw[2], hw[3]);
    lo = make_uint4(lw[0], lw[1], lw[2], lw[3]);
}

// ---- device scratch ----
__device__ int   g_counts[E_];
__device__ int   g_offsets[E_];
__device__ int   g_cursor[E_];
__device__ int   g_perm[NA];
__device__ __align__(16) __nv_bfloat16 g_h_hi[(size_t)NA * I_];
__device__ __align__(16) __nv_bfloat16 g_h_lo[(size_t)NA * I_];
__device__ __align__(16) float g_yp[(size_t)NA * H_];

// ---------------- routing ----------------
__global__ void k_zero() {
    int i = threadIdx.x;
    if (i < E_) { g_counts[i] = 0; g_cursor[i] = 0; }
}
__global__ void k_count(const int* __restrict__ ids) {
    int i = blockIdx.x * blockDim.x + threadIdx.x;
    if (i < NA) atomicAdd(&g_counts[ids[i]], 1);
}
__global__ void k_scan() {
    if (threadIdx.x == 0) {
        int acc = 0;
        for (int e = 0; e < E_; e++) { g_offsets[e] = acc; acc += g_counts[e]; }
    }
}
__global__ void k_scatter(const int* __restrict__ ids) {
    int i = blockIdx.x * blockDim.x + threadIdx.x;
    if (i < NA) {
        int e = ids[i];
        int p = atomicAdd(&g_cursor[e], 1);
        g_perm[g_offsets[e] + p] = i;
    }
}

// ---------------- gate+up mma GEMM ----------------
// SMEM stage layout (bytes): A_hi 0 (5120), A_lo 5120, Bg_hi 10240 (10240),
// Bg_lo 20480, Bu_hi 30720, Bu_lo 40960. Stage = 51200, double buffered.
#define GU_STAGE 51200
#define GU_SMEM  (2*GU_STAGE + 512)

__global__ void __launch_bounds__(256, 1) k_gateup_mma(
    const float* __restrict__ x,
    const float* __restrict__ Wg,
    const float* __restrict__ Wu)
{
    int e    = blockIdx.z;
    int cnt  = g_counts[e];
    int row0 = blockIdx.y * TM;
    if (row0 >= cnt) return;
    int off  = g_offsets[e];
    int col0 = blockIdx.x * TN;

    extern __shared__ char smem[];
    unsigned sb = smem_u32(smem);
    int tid = threadIdx.x;
    int wid = tid >> 5, l = tid & 31;
    int wm = wid & 3, wn = wid >> 2;

    int* toks = (int*)(smem + 2*GU_STAGE);
    if (tid < TM) {
        int r = row0 + tid;
        toks[tid] = g_perm[off + ((r < cnt) ? r : (cnt - 1))] >> 2;
    }
    __syncthreads();

    const float* wg = Wg + (size_t)e * I_ * H_ + (size_t)col0 * H_;
    const float* wu = Wu + (size_t)e * I_ * H_ + (size_t)col0 * H_;

    float cg[8][4], cu[8][4];
#pragma unroll
    for (int i = 0; i < 8; i++)
#pragma unroll
        for (int j = 0; j < 4; j++) { cg[i][j] = 0.f; cu[i][j] = 0.f; }

    int ar = tid >> 2, ac = (tid & 3) * 8;      // A: 64 rows x 32 cols, 8 floats/thread
    int br0 = tid >> 1 >> 1, bc0 = (tid & 3) * 8;  // = ar; B row seg 0
    (void)br0; (void)bc0;

    // ---- prologue: chunk 0 into stage 0 ----
    {
        char* st = smem;
        const float* px = x + (size_t)toks[ar] * H_ + ac;
        float4 a0 = *(const float4*)px, a1 = *(const float4*)(px + 4);
        uint4 hv, lv; cvt8(a0, a1, hv, lv);
        *(uint4*)(st + 0    + ar*RS + ac*2) = hv;
        *(uint4*)(st + 5120 + ar*RS + ac*2) = lv;
#pragma unroll
        for (int i = 0; i < 2; i++) {
            int u = tid + 256*i, r = u >> 2, c = (u & 3) * 8;
            const float* pg = wg + (size_t)r * H_ + c;
            float4 g0 = *(const float4*)pg, g1 = *(const float4*)(pg + 4);
            cvt8(g0, g1, hv, lv);
            *(uint4*)(st + 10240 + r*RS + c*2) = hv;
            *(uint4*)(st + 20480 + r*RS + c*2) = lv;
            const float* pu = wu + (size_t)r * H_ + c;
            float4 u0 = *(const float4*)pu, u1 = *(const float4*)(pu + 4);
            cvt8(u0, u1, hv, lv);
            *(uint4*)(st + 30720 + r*RS + c*2) = hv;
            *(uint4*)(st + 40960 + r*RS + c*2) = lv;
        }
    }
    __syncthreads();

    const int NK = H_ / KC;   // 64
    for (int k = 0; k < NK; k++) {
        int s = k & 1;
        bool pf = (k + 1 < NK);
        float4 pa0, pa1, pg0, pg1, pg2, pg3, pu0, pu1, pu2, pu3;
        if (pf) {
            int k0 = (k + 1) * KC;
            const float* px = x + (size_t)toks[ar] * H_ + k0 + ac;
            pa0 = *(const float4*)px; pa1 = *(const float4*)(px + 4);
            int u1i = tid + 256;
            int r0 = tid >> 2, c0 = (tid & 3) * 8;
            int r1 = u1i >> 2, c1 = (u1i & 3) * 8;
            const float* p;
            p = wg + (size_t)r0 * H_ + k0 + c0; pg0 = *(const float4*)p; pg1 = *(const float4*)(p + 4);
            p = wg + (size_t)r1 * H_ + k0 + c1; pg2 = *(const float4*)p; pg3 = *(const float4*)(p + 4);
            p = wu + (size_t)r0 * H_ + k0 + c0; pu0 = *(const float4*)p; pu1 = *(const float4*)(p + 4);
            p = wu + (size_t)r1 * H_ + k0 + c1; pu2 = *(const float4*)p; pu3 = *(const float4*)(p + 4);
        }

        // ---- compute on stage s ----
        unsigned stb = sb + s * GU_STAGE;
        unsigned arow = (unsigned)(wm*16 + (l & 15)) * RS;
#pragma unroll
        for (int kk = 0; kk < 2; kk++) {
            unsigned ak = (unsigned)(kk*16 + ((l >> 4) << 3)) * 2;
            unsigned ah[4], al[4];
            ldm4(ah, stb + 0    + arow + ak);
            ldm4(al, stb + 5120 + arow + ak);
            unsigned bbase = (unsigned)(wn*64 + ((l >> 4) & 1)*8 + (l & 7)) * RS
                           + (unsigned)(kk*16 + ((l >> 3) & 1)*8) * 2;
#pragma unroll
            for (int nt2 = 0; nt2 < 4; nt2++) {
                unsigned bo = bbase + nt2 * 16 * RS;
                unsigned bh[4], bl[4];
                ldm4(bh, stb + 10240 + bo);
                ldm4(bl, stb + 20480 + bo);
                mma4(cg[2*nt2],   ah, bh);   mma4(cg[2*nt2+1], ah, bh+2);
                mma4(cg[2*nt2],   al, bh);   mma4(cg[2*nt2+1], al, bh+2);
                mma4(cg[2*nt2],   ah, bl);   mma4(cg[2*nt2+1], ah, bl+2);
                ldm4(bh, stb + 30720 + bo);
                ldm4(bl, stb + 40960 + bo);
                mma4(cu[2*nt2],   ah, bh);   mma4(cu[2*nt2+1], ah, bh+2);
                mma4(cu[2*nt2],   al, bh);   mma4(cu[2*nt2+1], al, bh+2);
                mma4(cu[2*nt2],   ah, bl);   mma4(cu[2*nt2+1], ah, bl+2);
            }
        }

        if (pf) {
            char* st = smem + (s ^ 1) * GU_STAGE;
            uint4 hv, lv;
            cvt8(pa0, pa1, hv, lv);
            *(uint4*)(st + 0    + ar*RS + ac*2) = hv;
            *(uint4*)(st + 5120 + ar*RS + ac*2) = lv;
            int r0 = tid >> 2, c0 = (tid & 3) * 8;
            int u1i = tid + 256, r1 = u1i >> 2, c1 = (u1i & 3) * 8;
            cvt8(pg0, pg1, hv, lv);
            *(uint4*)(st + 10240 + r0*RS + c0*2) = hv;
            *(uint4*)(st + 20480 + r0*RS + c0*2) = lv;
            cvt8(pg2, pg3, hv, lv);
            *(uint4*)(st + 10240 + r1*RS + c1*2) = hv;
            *(uint4*)(st + 20480 + r1*RS + c1*2) = lv;
            cvt8(pu0, pu1, hv, lv);
            *(uint4*)(st + 30720 + r0*RS + c0*2) = hv;
            *(uint4*)(st + 40960 + r0*RS + c0*2) = lv;
            cvt8(pu2, pu3, hv, lv);
            *(uint4*)(st + 30720 + r1*RS + c1*2) = hv;
            *(uint4*)(st + 40960 + r1*RS + c1*2) = lv;
        }
        __syncthreads();
    }

    // ---- epilogue: h = silu(g)*u -> bf16 hi/lo ----
    int r0 = wm*16 + (l >> 2);
    int c0 = wn*64 + (l & 3) * 2;
#pragma unroll
    for (int nt = 0; nt < 8; nt++) {
        int col = col0 + c0 + nt*8;
#pragma unroll
        for (int half = 0; half < 2; half++) {
            int rr = r0 + half*8;
            if (row0 + rr < cnt) {
                float g0 = cg[nt][2*half],     u0 = cu[nt][2*half];
                float g1 = cg[nt][2*half + 1], u1 = cu[nt][2*half + 1];
                float h0 = (g0 / (1.f + __expf(-g0))) * u0;
                float h1 = (g1 / (1.f + __expf(-g1))) * u1;
                __nv_bfloat162 hb = __float22bfloat162_rn(make_float2(h0, h1));
                float2 hf = __bfloat1622float2(hb);
                __nv_bfloat162 lb = __float22bfloat162_rn(make_float2(h0 - hf.x, h1 - hf.y));
                size_t idx = (size_t)(off + row0 + rr) * I_ + col;
                *(unsigned*)&g_h_hi[idx] = *reinterpret_cast<unsigned*>(&hb);
                *(unsigned*)&g_h_lo[idx] = *reinterpret_cast<unsigned*>(&lb);
            }
        }
    }
}

// ---------------- down mma GEMM ----------------
// SMEM stage: A_hi 0 (5120), A_lo 5120, B_hi 10240 (10240), B_lo 20480. Stage 30720.
#define DN_STAGE 30720
#define DN_SMEM  (2*DN_STAGE + 512)

__global__ void __launch_bounds__(256, 2) k_down_mma(
    const float* __restrict__ Wd,
    const float* __restrict__ ew)
{
    int e    = blockIdx.z;
    int cnt  = g_counts[e];
    int row0 = blockIdx.y * TM;
    if (row0 >= cnt) return;
    int off  = g_offsets[e];
    int col0 = blockIdx.x * TN;

    extern __shared__ char smem[];
    unsigned sb = smem_u32(smem);
    int tid = threadIdx.x;
    int wid = tid >> 5, l = tid & 31;
    int wm = wid & 3, wn = wid >> 2;

    int* pvS = (int*)(smem + 2*DN_STAGE);
    if (tid < TM) {
        int r = row0 + tid;
        pvS[tid] = (r < cnt) ? g_perm[off + r] : -1;
    }
    __syncthreads();

    const float* wd = Wd + (size_t)e * H_ * I_ + (size_t)col0 * I_;

    float cd[8][4];
#pragma unroll
    for (int i = 0; i < 8; i++)
#pragma unroll
        for (int j = 0; j < 4; j++) cd[i][j] = 0.f;

    int ar = tid >> 2, ac = (tid & 3) * 8;
    int rrA = row0 + ar;
    size_t ga = (size_t)(off + ((rrA < cnt) ? rrA : (cnt - 1)));

    // prologue: chunk 0
    {
        char* st = smem;
        *(uint4*)(st + 0    + ar*RS + ac*2) = *(const uint4*)(&g_h_hi[ga*I_ + ac]);
        *(uint4*)(st + 5120 + ar*RS + ac*2) = *(const uint4*)(&g_h_lo[ga*I_ + ac]);
#pragma unroll
        for (int i = 0; i < 2; i++) {
            int u = tid + 256*i, r = u >> 2, c = (u & 3) * 8;
            const float* p = wd + (size_t)r * I_ + c;
            float4 b0 = *(const float4*)p, b1 = *(const float4*)(p + 4);
            uint4 hv, lv; cvt8(b0, b1, hv, lv);
            *(uint4*)(st + 10240 + r*RS + c*2) = hv;
            *(uint4*)(st + 20480 + r*RS + c*2) = lv;
        }
    }
    __syncthreads();

    const int NK = I_ / KC;   // 24
    for (int k = 0; k < NK; k++) {
        int s = k & 1;
        bool pf = (k + 1 < NK);
        uint4 pah, pal; float4 pb0, pb1, pb2, pb3;
        if (pf) {
            int k0 = (k + 1) * KC;
            pah = *(const uint4*)(&g_h_hi[ga*I_ + k0 + ac]);
            pal = *(const uint4*)(&g_h_lo[ga*I_ + k0 + ac]);
            int r0 = tid >> 2, c0 = (tid & 3) * 8;
            int u1i = tid + 256, r1 = u1i >> 2, c1 = (u1i & 3) * 8;
            const float* p;
            p = wd + (size_t)r0 * I_ + k0 + c0; pb0 = *(const float4*)p; pb1 = *(const float4*)(p + 4);
            p = wd + (size_t)r1 * I_ + k0 + c1; pb2 = *(const float4*)p; pb3 = *(const float4*)(p + 4);
        }

        unsigned stb = sb + s * DN_STAGE;
        unsigned arow = (unsigned)(wm*16 + (l & 15)) * RS;
#pragma unroll
        for (int kk = 0; kk < 2; kk++) {
            unsigned ak = (unsigned)(kk*16 + ((l >> 4) << 3)) * 2;
            unsigned ah[4], al[4];
            ldm4(ah, stb + 0    + arow + ak);
            ldm4(al, stb + 5120 + arow + ak);
            unsigned bbase = (unsigned)(wn*64 + ((l >> 4) & 1)*8 + (l & 7)) * RS
                           + (unsigned)(kk*16 + ((l >> 3) & 1)*8) * 2;
#pragma unroll
            for (int nt2 = 0; nt2 < 4; nt2++) {
                unsigned bo = bbase + nt2 * 16 * RS;
                unsigned bh[4], bl[4];
                ldm4(bh, stb + 10240 + bo);
                ldm4(bl, stb + 20480 + bo);
                mma4(cd[2*nt2],   ah, bh);   mma4(cd[2*nt2+1], ah, bh+2);
                mma4(cd[2*nt2],   al, bh);   mma4(cd[2*nt2+1], al, bh+2);
                mma4(cd[2*nt2],   ah, bl);   mma4(cd[2*nt2+1], ah, bl+2);
            }
        }

        if (pf) {
            char* st = smem + (s ^ 1) * DN_STAGE;
            *(uint4*)(st + 0    + ar*RS + ac*2) = pah;
            *(uint4*)(st + 5120 + ar*RS + ac*2) = pal;
            int r0 = tid >> 2, c0 = (tid & 3) * 8;
            int u1i = tid + 256, r1 = u1i >> 2, c1 = (u1i & 3) * 8;
            uint4 hv, lv;
            cvt8(pb0, pb1, hv, lv);
            *(uint4*)(st + 10240 + r0*RS + c0*2) = hv;
            *(uint4*)(st + 20480 + r0*RS + c0*2) = lv;
            cvt8(pb2, pb3, hv, lv);
            *(uint4*)(st + 10240 + r1*RS + c1*2) = hv;
            *(uint4*)(st + 20480 + r1*RS + c1*2) = lv;
        }
        __syncthreads();
    }

    // epilogue: scale by router weight, scatter to g_yp
    int r0 = wm*16 + (l >> 2);
    int c0 = wn*64 + (l & 3) * 2;
#pragma unroll
    for (int half = 0; half < 2; half++) {
        int rr = r0 + half*8;
        int pv = (rr < TM) ? pvS[rr] : -1;
        if (pv >= 0) {
            float w = ew[pv];
            size_t base = (size_t)pv * H_ + col0 + c0;
#pragma unroll
            for (int nt = 0; nt < 8; nt++) {
                float2 v = make_float2(w * cd[nt][2*half], w * cd[nt][2*half + 1]);
                *(float2*)(&g_yp[base + nt*8]) = v;
            }
        }
    }
}

// ---------------- combine ----------------
__global__ void k_combine(float* __restrict__ y) {
    int i = blockIdx.x * blockDim.x + threadIdx.x;   // over T_*H_/4
    if (i < T_ * H_ / 4) {
        int t  = i / (H_ / 4);
        int h4 = i - t * (H_ / 4);
        const float4* p = (const float4*)(&g_yp[(size_t)(t * K_) * H_]) + h4;
        float4 a = p[0];
        float4 b = p[H_ / 4];
        float4 c = p[2 * (H_ / 4)];
        float4 d = p[3 * (H_ / 4)];
        float4 o;
        o.x = a.x + b.x + c.x + d.x;
        o.y = a.y + b.y + c.y + d.y;
        o.z = a.z + b.z + c.z + d.z;
        o.w = a.w + b.w + c.w + d.w;
        ((float4*)y)[i] = o;
    }
}

// ---------------- launch ----------------
extern "C" void kernel_launch(void* const* d_in, const int* in_sizes, int n_in,
                              void* d_out, int out_size)
{
    const float* x   = (const float*)d_in[0];
    const float* Wg  = (const float*)d_in[1];
    const float* Wu  = (const float*)d_in[2];
    const float* Wd  = (const float*)d_in[3];
    const int*   ids = (const int*)d_in[4];
    const float* ew  = (const float*)d_in[5];
    float*       y   = (float*)d_out;

    cudaFuncSetAttribute(k_gateup_mma, cudaFuncAttributeMaxDynamicSharedMemorySize, GU_SMEM);
    cudaFuncSetAttribute(k_down_mma,   cudaFuncAttributeMaxDynamicSharedMemorySize, DN_SMEM);

    k_zero<<<1, 32>>>();
    k_count<<<NA / 256, 256>>>(ids);
    k_scan<<<1, 1>>>();
    k_scatter<<<NA / 256, 256>>>(ids);

    dim3 gA(I_ / TN, NA / TM, E_);   // (6, 64, 32)
    k_gateup_mma<<<gA, 256, GU_SMEM>>>(x, Wg, Wu);

    dim3 gB(H_ / TN, NA / TM, E_);   // (16, 64, 32)
    k_down_mma<<<gB, 256, DN_SMEM>>>(Wd, ew);

    k_combine<<<(T_ * H_ / 4 + 255) / 256, 256>>>(y);
}

// round 4
// speedup vs baseline: 2.3379x; 1.1103x over previous
#include <cuda_runtime.h>
#include <cuda_bf16.h>

// Problem constants
#define T_  1024
#define H_  2048
#define I_  768
#define E_  32
#define K_  4
#define NA  (T_*K_)   // 4096 assignment rows

// GEMM tiling
#define TM  64
#define TN  128
#define KC  32
#define RS  80        // SMEM row stride in bytes (32 bf16 + 16B pad) — conflict-free ldmatrix

// ---------------- portable PTX helpers ----------------
__device__ __forceinline__ unsigned smem_u32(const void* p) {
    unsigned a;
    asm("{ .reg .u64 t; cvta.to.shared.u64 t, %1; cvt.u32.u64 %0, t; }" : "=r"(a) : "l"(p));
    return a;
}

__device__ __forceinline__ void ldm4(unsigned* d, unsigned a) {
    asm volatile("ldmatrix.sync.aligned.m8n8.x4.shared.b16 {%0,%1,%2,%3}, [%4];"
        : "=r"(d[0]), "=r"(d[1]), "=r"(d[2]), "=r"(d[3]) : "r"(a));
}

__device__ __forceinline__ void mma4(float* c, const unsigned* a, const unsigned* b) {
    asm volatile("mma.sync.aligned.m16n8k16.row.col.f32.bf16.bf16.f32 "
        "{%0,%1,%2,%3},{%4,%5,%6,%7},{%8,%9},{%0,%1,%2,%3};"
        : "+f"(c[0]), "+f"(c[1]), "+f"(c[2]), "+f"(c[3])
        : "r"(a[0]), "r"(a[1]), "r"(a[2]), "r"(a[3]), "r"(b[0]), "r"(b[1]));
}

// split 8 fp32 -> 8 bf16 hi + 8 bf16 lo (packed into uint4 each)
__device__ __forceinline__ void cvt8(float4 a, float4 b, uint4& hi, uint4& lo) {
    float va[8] = {a.x, a.y, a.z, a.w, b.x, b.y, b.z, b.w};
    unsigned hw[4], lw[4];
#pragma unroll
    for (int j = 0; j < 4; j++) {
        float2 f = make_float2(va[2*j], va[2*j+1]);
        __nv_bfloat162 h = __float22bfloat162_rn(f);
        float2 hf = __bfloat1622float2(h);
        __nv_bfloat162 l = __float22bfloat162_rn(make_float2(f.x - hf.x, f.y - hf.y));
        hw[j] = *reinterpret_cast<unsigned*>(&h);
        lw[j] = *reinterpret_cast<unsigned*>(&l);
    }
    hi = make_uint4(hw[0], hw[1], hw[2], hw[3]);
    lo = make_uint4(lw[0], lw[1], lw[2], lw[3]);
}

// ---- device scratch ----
__device__ int   g_counts[E_];
__device__ int   g_offsets[E_];
__device__ int   g_perm[NA];
__device__ __align__(16) __nv_bfloat16 g_h_hi[(size_t)NA * I_];
__device__ __align__(16) __nv_bfloat16 g_h_lo[(size_t)NA * I_];
__device__ __align__(16) float g_yp[(size_t)NA * H_];

// ---------------- routing: one block does count+scan+scatter ----------------
__global__ void k_route(const int* __restrict__ ids) {
    __shared__ int cnt[E_], offs[E_], cur[E_];
    int tid = threadIdx.x;   // 1024
    if (tid < E_) { cnt[tid] = 0; cur[tid] = 0; }
    __syncthreads();
    for (int i = tid; i < NA; i += 1024) atomicAdd(&cnt[ids[i]], 1);
    __syncthreads();
    if (tid == 0) {
        int acc = 0;
        for (int e = 0; e < E_; e++) {
            offs[e] = acc; g_offsets[e] = acc; g_counts[e] = cnt[e]; acc += cnt[e];
        }
    }
    __syncthreads();
    for (int i = tid; i < NA; i += 1024) {
        int e = ids[i];
        int p = atomicAdd(&cur[e], 1);
        g_perm[offs[e] + p] = i;
    }
}

// ---------------- gate+up mma GEMM ----------------
// SMEM stage (bytes): A_hi 0 (5120), A_lo 5120, Bg_hi 10240 (10240),
// Bg_lo 20480, Bu_hi 30720, Bu_lo 40960. Stage 51200, double buffered.
#define GU_STAGE 51200
#define GU_SMEM  (2*GU_STAGE + 512)
#define HST      272                 // h-staging row stride

__global__ void __launch_bounds__(256, 1) k_gateup_mma(
    const float* __restrict__ x,
    const float* __restrict__ Wg,
    const float* __restrict__ Wu)
{
    int e    = blockIdx.z;
    int cnt  = g_counts[e];
    int row0 = blockIdx.y * TM;
    if (row0 >= cnt) return;
    int off  = g_offsets[e];
    int col0 = blockIdx.x * TN;

    extern __shared__ char smem[];
    unsigned sb = smem_u32(smem);
    int tid = threadIdx.x;
    int wid = tid >> 5, l = tid & 31;
    int wm = wid & 1, wn = wid >> 1;     // 2 x 4 warp grid, warp tile 32x32

    int* toks = (int*)(smem + 2*GU_STAGE);
    if (tid < TM) {
        int r = row0 + tid;
        toks[tid] = g_perm[off + ((r < cnt) ? r : (cnt - 1))] >> 2;
    }
    __syncthreads();

    const float* wg = Wg + (size_t)e * I_ * H_ + (size_t)col0 * H_;
    const float* wu = Wu + (size_t)e * I_ * H_ + (size_t)col0 * H_;

    float cg[2][4][4], cu[2][4][4];
#pragma unroll
    for (int mt = 0; mt < 2; mt++)
#pragma unroll
        for (int nt = 0; nt < 4; nt++)
#pragma unroll
            for (int j = 0; j < 4; j++) { cg[mt][nt][j] = 0.f; cu[mt][nt][j] = 0.f; }

    int ar = tid >> 2, ac = (tid & 3) * 8;   // A fill: 64 rows x 32 cols, 8 fp32/thread

    // ---- prologue: chunk 0 into stage 0 ----
    {
        char* st = smem;
        const float* px = x + (size_t)toks[ar] * H_ + ac;
        float4 a0 = *(const float4*)px, a1 = *(const float4*)(px + 4);
        uint4 hv, lv; cvt8(a0, a1, hv, lv);
        *(uint4*)(st + 0    + ar*RS + ac*2) = hv;
        *(uint4*)(st + 5120 + ar*RS + ac*2) = lv;
#pragma unroll
        for (int i = 0; i < 2; i++) {
            int u = tid + 256*i, r = u >> 2, c = (u & 3) * 8;
            const float* pg = wg + (size_t)r * H_ + c;
            float4 g0 = *(const float4*)pg, g1 = *(const float4*)(pg + 4);
            cvt8(g0, g1, hv, lv);
            *(uint4*)(st + 10240 + r*RS + c*2) = hv;
            *(uint4*)(st + 20480 + r*RS + c*2) = lv;
            const float* pu = wu + (size_t)r * H_ + c;
            float4 u0 = *(const float4*)pu, u1 = *(const float4*)(pu + 4);
            cvt8(u0, u1, hv, lv);
            *(uint4*)(st + 30720 + r*RS + c*2) = hv;
            *(uint4*)(st + 40960 + r*RS + c*2) = lv;
        }
    }
    __syncthreads();

    const int NK = H_ / KC;   // 64
    for (int k = 0; k < NK; k++) {
        int s = k & 1;
        bool pf = (k + 1 < NK);
        float4 pa0, pa1, pg0, pg1, pg2, pg3, pu0, pu1, pu2, pu3;
        if (pf) {
            int k0 = (k + 1) * KC;
            const float* px = x + (size_t)toks[ar] * H_ + k0 + ac;
            pa0 = *(const float4*)px; pa1 = *(const float4*)(px + 4);
            int r0 = tid >> 2, c0 = (tid & 3) * 8;
            int u1i = tid + 256, r1 = u1i >> 2, c1 = (u1i & 3) * 8;
            const float* p;
            p = wg + (size_t)r0 * H_ + k0 + c0; pg0 = *(const float4*)p; pg1 = *(const float4*)(p + 4);
            p = wg + (size_t)r1 * H_ + k0 + c1; pg2 = *(const float4*)p; pg3 = *(const float4*)(p + 4);
            p = wu + (size_t)r0 * H_ + k0 + c0; pu0 = *(const float4*)p; pu1 = *(const float4*)(p + 4);
            p = wu + (size_t)r1 * H_ + k0 + c1; pu2 = *(const float4*)p; pu3 = *(const float4*)(p + 4);
        }

        // ---- compute on stage s ----
        unsigned stb = sb + s * GU_STAGE;
#pragma unroll
        for (int kk = 0; kk < 2; kk++) {
            unsigned ah[2][4], al[2][4];
#pragma unroll
            for (int mt = 0; mt < 2; mt++) {
                unsigned arow = (unsigned)(wm*32 + mt*16 + (l & 15)) * RS;
                unsigned ak   = (unsigned)(kk*16 + ((l >> 4) << 3)) * 2;
                ldm4(ah[mt], stb + 0    + arow + ak);
                ldm4(al[mt], stb + 5120 + arow + ak);
            }
#pragma unroll
            for (int nt16 = 0; nt16 < 2; nt16++) {
                unsigned bro = (unsigned)(wn*32 + nt16*16 + ((l >> 4) & 1)*8 + (l & 7)) * RS
                             + (unsigned)(kk*16 + ((l >> 3) & 1)*8) * 2;
                unsigned bh[4], bl[4];
                ldm4(bh, stb + 10240 + bro);
                ldm4(bl, stb + 20480 + bro);
#pragma unroll
                for (int mt = 0; mt < 2; mt++) {
                    mma4(cg[mt][2*nt16],   ah[mt], bh);   mma4(cg[mt][2*nt16+1], ah[mt], bh+2);
                    mma4(cg[mt][2*nt16],   al[mt], bh);   mma4(cg[mt][2*nt16+1], al[mt], bh+2);
                    mma4(cg[mt][2*nt16],   ah[mt], bl);   mma4(cg[mt][2*nt16+1], ah[mt], bl+2);
                }
                ldm4(bh, stb + 30720 + bro);
                ldm4(bl, stb + 40960 + bro);
#pragma unroll
                for (int mt = 0; mt < 2; mt++) {
                    mma4(cu[mt][2*nt16],   ah[mt], bh);   mma4(cu[mt][2*nt16+1], ah[mt], bh+2);
                    mma4(cu[mt][2*nt16],   al[mt], bh);   mma4(cu[mt][2*nt16+1], al[mt], bh+2);
                    mma4(cu[mt][2*nt16],   ah[mt], bl);   mma4(cu[mt][2*nt16+1], ah[mt], bl+2);
                }
            }
        }

        if (pf) {
            char* st = smem + (s ^ 1) * GU_STAGE;
            uint4 hv, lv;
            cvt8(pa0, pa1, hv, lv);
            *(uint4*)(st + 0    + ar*RS + ac*2) = hv;
            *(uint4*)(st + 5120 + ar*RS + ac*2) = lv;
            int r0 = tid >> 2, c0 = (tid & 3) * 8;
            int u1i = tid + 256, r1 = u1i >> 2, c1 = (u1i & 3) * 8;
            cvt8(pg0, pg1, hv, lv);
            *(uint4*)(st + 10240 + r0*RS + c0*2) = hv;
            *(uint4*)(st + 20480 + r0*RS + c0*2) = lv;
            cvt8(pg2, pg3, hv, lv);
            *(uint4*)(st + 10240 + r1*RS + c1*2) = hv;
            *(uint4*)(st + 20480 + r1*RS + c1*2) = lv;
            cvt8(pu0, pu1, hv, lv);
            *(uint4*)(st + 30720 + r0*RS + c0*2) = hv;
            *(uint4*)(st + 40960 + r0*RS + c0*2) = lv;
            cvt8(pu2, pu3, hv, lv);
            *(uint4*)(st + 30720 + r1*RS + c1*2) = hv;
            *(uint4*)(st + 40960 + r1*RS + c1*2) = lv;
        }
        __syncthreads();
    }

    // ---- epilogue: h = silu(g)*u -> staged in SMEM, coalesced store ----
    char* sh_hi = smem;               // 64 x HST = 17408 B
    char* sh_lo = smem + 64*HST;      // another 17408 B (fits in stage area)
#pragma unroll
    for (int mt = 0; mt < 2; mt++)
#pragma unroll
        for (int nt = 0; nt < 4; nt++)
#pragma unroll
            for (int half = 0; half < 2; half++) {
                int rr = wm*32 + mt*16 + (l >> 2) + half*8;
                int cc = wn*32 + nt*8 + (l & 3)*2;
                float g0 = cg[mt][nt][2*half],   g1 = cg[mt][nt][2*half+1];
                float u0 = cu[mt][nt][2*half],   u1 = cu[mt][nt][2*half+1];
                float h0 = (g0 / (1.f + __expf(-g0))) * u0;
                float h1 = (g1 / (1.f + __expf(-g1))) * u1;
                __nv_bfloat162 hb = __float22bfloat162_rn(make_float2(h0, h1));
                float2 hf = __bfloat1622float2(hb);
                __nv_bfloat162 lb = __float22bfloat162_rn(make_float2(h0 - hf.x, h1 - hf.y));
                *(unsigned*)(sh_hi + rr*HST + cc*2) = *reinterpret_cast<unsigned*>(&hb);
                *(unsigned*)(sh_lo + rr*HST + cc*2) = *reinterpret_cast<unsigned*>(&lb);
            }
    __syncthreads();
#pragma unroll
    for (int j = 0; j < 4; j++) {
        int u = tid + 256*j;
        int r = u >> 4, c16 = u & 15;
        if (row0 + r < cnt) {
            size_t gidx = (size_t)(off + row0 + r) * I_ + col0 + c16*8;
            *(uint4*)&g_h_hi[gidx] = *(uint4*)(sh_hi + r*HST + c16*16);
            *(uint4*)&g_h_lo[gidx] = *(uint4*)(sh_lo + r*HST + c16*16);
        }
    }
}

// ---------------- down mma GEMM ----------------
// SMEM stage: A_hi 0 (5120), A_lo 5120, B_hi 10240 (10240), B_lo 20480. Stage 30720.
#define DN_STAGE 30720
#define DN_SMEM  (2*DN_STAGE + 512)

__global__ void __launch_bounds__(256, 2) k_down_mma(
    const float* __restrict__ Wd,
    const float* __restrict__ ew)
{
    int e    = blockIdx.z;
    int cnt  = g_counts[e];
    int row0 = blockIdx.y * TM;
    if (row0 >= cnt) return;
    int off  = g_offsets[e];
    int col0 = blockIdx.x * TN;

    extern __shared__ char smem[];
    unsigned sb = smem_u32(smem);
    int tid = threadIdx.x;
    int wid = tid >> 5, l = tid & 31;
    int wm = wid & 1, wn = wid >> 1;

    int* pvS = (int*)(smem + 2*DN_STAGE);
    if (tid < TM) {
        int r = row0 + tid;
        pvS[tid] = (r < cnt) ? g_perm[off + r] : -1;
    }
    __syncthreads();

    const float* wd = Wd + (size_t)e * H_ * I_ + (size_t)col0 * I_;

    float cd[2][4][4];
#pragma unroll
    for (int mt = 0; mt < 2; mt++)
#pragma unroll
        for (int nt = 0; nt < 4; nt++)
#pragma unroll
            for (int j = 0; j < 4; j++) cd[mt][nt][j] = 0.f;

    int ar = tid >> 2, ac = (tid & 3) * 8;
    int rrA = row0 + ar;
    size_t ga = (size_t)(off + ((rrA < cnt) ? rrA : (cnt - 1)));

    // prologue: chunk 0
    {
        char* st = smem;
        *(uint4*)(st + 0    + ar*RS + ac*2) = *(const uint4*)(&g_h_hi[ga*I_ + ac]);
        *(uint4*)(st + 5120 + ar*RS + ac*2) = *(const uint4*)(&g_h_lo[ga*I_ + ac]);
#pragma unroll
        for (int i = 0; i < 2; i++) {
            int u = tid + 256*i, r = u >> 2, c = (u & 3) * 8;
            const float* p = wd + (size_t)r * I_ + c;
            float4 b0 = *(const float4*)p, b1 = *(const float4*)(p + 4);
            uint4 hv, lv; cvt8(b0, b1, hv, lv);
            *(uint4*)(st + 10240 + r*RS + c*2) = hv;
            *(uint4*)(st + 20480 + r*RS + c*2) = lv;
        }
    }
    __syncthreads();

    const int NK = I_ / KC;   // 24
    for (int k = 0; k < NK; k++) {
        int s = k & 1;
        bool pf = (k + 1 < NK);
        uint4 pah, pal; float4 pb0, pb1, pb2, pb3;
        if (pf) {
            int k0 = (k + 1) * KC;
            pah = *(const uint4*)(&g_h_hi[ga*I_ + k0 + ac]);
            pal = *(const uint4*)(&g_h_lo[ga*I_ + k0 + ac]);
            int r0 = tid >> 2, c0 = (tid & 3) * 8;
            int u1i = tid + 256, r1 = u1i >> 2, c1 = (u1i & 3) * 8;
            const float* p;
            p = wd + (size_t)r0 * I_ + k0 + c0; pb0 = *(const float4*)p; pb1 = *(const float4*)(p + 4);
            p = wd + (size_t)r1 * I_ + k0 + c1; pb2 = *(const float4*)p; pb3 = *(const float4*)(p + 4);
        }

        unsigned stb = sb + s * DN_STAGE;
#pragma unroll
        for (int kk = 0; kk < 2; kk++) {
            unsigned ah[2][4], al[2][4];
#pragma unroll
            for (int mt = 0; mt < 2; mt++) {
                unsigned arow = (unsigned)(wm*32 + mt*16 + (l & 15)) * RS;
                unsigned ak   = (unsigned)(kk*16 + ((l >> 4) << 3)) * 2;
                ldm4(ah[mt], stb + 0    + arow + ak);
                ldm4(al[mt], stb + 5120 + arow + ak);
            }
#pragma unroll
            for (int nt16 = 0; nt16 < 2; nt16++) {
                unsigned bro = (unsigned)(wn*32 + nt16*16 + ((l >> 4) & 1)*8 + (l & 7)) * RS
                             + (unsigned)(kk*16 + ((l >> 3) & 1)*8) * 2;
                unsigned bh[4], bl[4];
                ldm4(bh, stb + 10240 + bro);
                ldm4(bl, stb + 20480 + bro);
#pragma unroll
                for (int mt = 0; mt < 2; mt++) {
                    mma4(cd[mt][2*nt16],   ah[mt], bh);   mma4(cd[mt][2*nt16+1], ah[mt], bh+2);
                    mma4(cd[mt][2*nt16],   al[mt], bh);   mma4(cd[mt][2*nt16+1], al[mt], bh+2);
                    mma4(cd[mt][2*nt16],   ah[mt], bl);   mma4(cd[mt][2*nt16+1], ah[mt], bl+2);
                }
            }
        }

        if (pf) {
            char* st = smem + (s ^ 1) * DN_STAGE;
            *(uint4*)(st + 0    + ar*RS + ac*2) = pah;
            *(uint4*)(st + 5120 + ar*RS + ac*2) = pal;
            int r0 = tid >> 2, c0 = (tid & 3) * 8;
            int u1i = tid + 256, r1 = u1i >> 2, c1 = (u1i & 3) * 8;
            uint4 hv, lv;
            cvt8(pb0, pb1, hv, lv);
            *(uint4*)(st + 10240 + r0*RS + c0*2) = hv;
            *(uint4*)(st + 20480 + r0*RS + c0*2) = lv;
            cvt8(pb2, pb3, hv, lv);
            *(uint4*)(st + 10240 + r1*RS + c1*2) = hv;
            *(uint4*)(st + 20480 + r1*RS + c1*2) = lv;
        }
        __syncthreads();
    }

    // epilogue: scale by router weight, scatter to g_yp
#pragma unroll
    for (int mt = 0; mt < 2; mt++)
#pragma unroll
        for (int half = 0; half < 2; half++) {
            int rr = wm*32 + mt*16 + (l >> 2) + half*8;
            int pv = pvS[rr];
            if (pv >= 0) {
                float w = ew[pv];
                size_t base = (size_t)pv * H_ + col0 + wn*32 + (l & 3)*2;
#pragma unroll
                for (int nt = 0; nt < 4; nt++) {
                    float2 v = make_float2(w * cd[mt][nt][2*half], w * cd[mt][nt][2*half+1]);
                    *(float2*)(&g_yp[base + nt*8]) = v;
                }
            }
        }
}

// ---------------- combine ----------------
__global__ void k_combine(float* __restrict__ y) {
    int i = blockIdx.x * blockDim.x + threadIdx.x;   // over T_*H_/4
    if (i < T_ * H_ / 4) {
        int t  = i / (H_ / 4);
        int h4 = i - t * (H_ / 4);
        const float4* p = (const float4*)(&g_yp[(size_t)(t * K_) * H_]) + h4;
        float4 a = p[0];
        float4 b = p[H_ / 4];
        float4 c = p[2 * (H_ / 4)];
        float4 d = p[3 * (H_ / 4)];
        float4 o;
        o.x = a.x + b.x + c.x + d.x;
        o.y = a.y + b.y + c.y + d.y;
        o.z = a.z + b.z + c.z + d.z;
        o.w = a.w + b.w + c.w + d.w;
        ((float4*)y)[i] = o;
    }
}

// ---------------- launch ----------------
extern "C" void kernel_launch(void* const* d_in, const int* in_sizes, int n_in,
                              void* d_out, int out_size)
{
    const float* x   = (const float*)d_in[0];
    const float* Wg  = (const float*)d_in[1];
    const float* Wu  = (const float*)d_in[2];
    const float* Wd  = (const float*)d_in[3];
    const int*   ids = (const int*)d_in[4];
    const float* ew  = (const float*)d_in[5];
    float*       y   = (float*)d_out;

    cudaFuncSetAttribute(k_gateup_mma, cudaFuncAttributeMaxDynamicSharedMemorySize, GU_SMEM);
    cudaFuncSetAttribute(k_down_mma,   cudaFuncAttributeMaxDynamicSharedMemorySize, DN_SMEM);

    k_route<<<1, 1024>>>(ids);

    dim3 gA(I_ / TN, NA / TM, E_);   // (6, 64, 32)
    k_gateup_mma<<<gA, 256, GU_SMEM>>>(x, Wg, Wu);

    dim3 gB(H_ / TN, NA / TM, E_);   // (16, 64, 32)
    k_down_mma<<<gB, 256, DN_SMEM>>>(Wd, ew);

    k_combine<<<(T_ * H_ / 4 + 255) / 256, 256>>>(y);
}